// round 1
// baseline (speedup 1.0000x reference)
#include <cuda_runtime.h>

#define T_TOK 4096
#define E_DIM 768
#define HN 12
#define RN 16
#define HD 64
#define ER 12288

// Scratch (allocation-free rule: __device__ globals)
__device__ float g_q[T_TOK * E_DIM];        // scaled query projection [t, h*64+d]
__device__ float g_attn[T_TOK * HN * RN];   // softmax over rules [t, h, r]
__device__ float g_mid[T_TOK * E_DIM];      // torch-scrambled pre-Wo activations

// ---------------------------------------------------------------------------
// Generic 4096x768x768 GEMM: C = (A @ W + bias) * scale
// mode 0: A = Ap (external), C = g_q      (query projection)
// mode 1: A = g_mid,        C = Cp       (output projection)
// Tiling: BM=128, BN=64, BK=16, 256 threads, 8x4 per-thread microtile.
// ---------------------------------------------------------------------------
__global__ __launch_bounds__(256) void gemm768_kernel(
    const float* __restrict__ Ap, const float* __restrict__ W,
    const float* __restrict__ bias, float* __restrict__ Cp,
    float scale, int mode)
{
    const float* A = (mode == 0) ? Ap : g_mid;
    float*       C = (mode == 0) ? g_q : Cp;

    __shared__ float As[16][128];
    __shared__ float Bs[16][64];

    int tid = threadIdx.x;
    int tx = tid & 15, ty = tid >> 4;
    int m0 = blockIdx.y * 128;
    int n0 = blockIdx.x * 64;

    float acc[8][4];
#pragma unroll
    for (int i = 0; i < 8; i++)
#pragma unroll
        for (int j = 0; j < 4; j++) acc[i][j] = 0.f;

    for (int k0 = 0; k0 < E_DIM; k0 += 16) {
#pragma unroll
        for (int it = 0; it < 2; it++) {
            int f = tid + it * 256;            // 0..511 float4s of the A tile
            int row = f >> 2, kq = (f & 3) << 2;
            float4 v = *reinterpret_cast<const float4*>(&A[(m0 + row) * E_DIM + k0 + kq]);
            As[kq + 0][row] = v.x; As[kq + 1][row] = v.y;
            As[kq + 2][row] = v.z; As[kq + 3][row] = v.w;
        }
        {
            int row = tid >> 4, cq = (tid & 15) << 2;
            *reinterpret_cast<float4*>(&Bs[row][cq]) =
                *reinterpret_cast<const float4*>(&W[(k0 + row) * E_DIM + n0 + cq]);
        }
        __syncthreads();
#pragma unroll
        for (int k = 0; k < 16; k++) {
            float4 a0 = *reinterpret_cast<const float4*>(&As[k][ty * 8]);
            float4 a1 = *reinterpret_cast<const float4*>(&As[k][ty * 8 + 4]);
            float4 bq4 = *reinterpret_cast<const float4*>(&Bs[k][tx * 4]);
            float av[8] = {a0.x, a0.y, a0.z, a0.w, a1.x, a1.y, a1.z, a1.w};
            float bw[4] = {bq4.x, bq4.y, bq4.z, bq4.w};
#pragma unroll
            for (int i = 0; i < 8; i++)
#pragma unroll
                for (int j = 0; j < 4; j++)
                    acc[i][j] = fmaf(av[i], bw[j], acc[i][j]);
        }
        __syncthreads();
    }

    float4 bb = *reinterpret_cast<const float4*>(&bias[n0 + tx * 4]);
    float bl[4] = {bb.x, bb.y, bb.z, bb.w};
#pragma unroll
    for (int i = 0; i < 8; i++) {
        float4 o;
        o.x = (acc[i][0] + bl[0]) * scale;
        o.y = (acc[i][1] + bl[1]) * scale;
        o.z = (acc[i][2] + bl[2]) * scale;
        o.w = (acc[i][3] + bl[3]) * scale;
        *reinterpret_cast<float4*>(&C[(m0 + ty * 8 + i) * E_DIM + n0 + tx * 4]) = o;
    }
}

// ---------------------------------------------------------------------------
// Fuzzy membership + softmax over rules. One thread per (t, h, r).
// z = -0.5 * mean_d( ((q - rk)/rw)^2 ); softmax over the 16-lane rule group.
// ---------------------------------------------------------------------------
__global__ __launch_bounds__(256) void attn_kernel(
    const float* __restrict__ rk, const float* __restrict__ rw)
{
    int gid = blockIdx.x * blockDim.x + threadIdx.x;   // exactly T*H*R launched
    int r  = gid & 15;
    int th = gid >> 4;
    int h  = th % HN;
    int t  = th / HN;

    const float* qp  = &g_q[t * E_DIM + h * HD];
    const float* rkp = &rk[(h * RN + r) * HD];
    const float* rwp = &rw[(h * RN + r) * HD];

    float s = 0.f;
#pragma unroll
    for (int d = 0; d < HD; d++) {
        float diff = (qp[d] - rkp[d]) / rwp[d];        // |.| irrelevant after squaring
        s = fmaf(diff, diff, s);
    }
    float z = -0.5f * s * (1.0f / 64.0f);

    float m = z;
#pragma unroll
    for (int o = 8; o; o >>= 1) m = fmaxf(m, __shfl_xor_sync(0xffffffffu, m, o));
    float e = expf(z - m);
    float sum = e;
#pragma unroll
    for (int o = 8; o; o >>= 1) sum += __shfl_xor_sync(0xffffffffu, sum, o);

    g_attn[gid] = e / sum;
}

// ---------------------------------------------------------------------------
// Fused value@Wv GEMM + attn-weighted rule reduction + torch-faithful scatter.
// C tile: 128 tokens x 64 Wv cols = 4 (h,d) pairs x 16 rules (one head/block).
// Epilogue: mid[t, scramble(h, s, d)] = sum_r attn[t,h,r] * (acc + bv)*scale.
// ---------------------------------------------------------------------------
__global__ __launch_bounds__(256) void fused_v_kernel(
    const float* __restrict__ Vin, const float* __restrict__ Wv,
    const float* __restrict__ bv)
{
    __shared__ float As[16][128];
    __shared__ float Bs[16][64];
    __shared__ float attn_s[128][17];      // +1 pad: conflict-free epilogue reads
    __shared__ float red_s[128][4][4];     // [token][d-local][tx&3 partial]

    int tid = threadIdx.x;
    int tx = tid & 15, ty = tid >> 4;
    int m0 = blockIdx.y * 128;
    int n0 = blockIdx.x * 64;              // Wv column base
    int h = n0 >> 10;                      // head  (1024 cols per head)
    int dbase = (n0 & 1023) >> 4;          // d base within head (4 d's per block)

    // Prefetch this block's attn tile [128 tokens x 16 rules]
#pragma unroll
    for (int it = 0; it < 8; it++) {
        int f = tid + it * 256;            // 0..2047
        int row = f >> 4, r = f & 15;
        attn_s[row][r] = g_attn[(m0 + row) * (HN * RN) + h * RN + r];
    }

    float acc[8][4];
#pragma unroll
    for (int i = 0; i < 8; i++)
#pragma unroll
        for (int j = 0; j < 4; j++) acc[i][j] = 0.f;

    for (int k0 = 0; k0 < E_DIM; k0 += 16) {
#pragma unroll
        for (int it = 0; it < 2; it++) {
            int f = tid + it * 256;
            int row = f >> 2, kq = (f & 3) << 2;
            float4 v = *reinterpret_cast<const float4*>(&Vin[(m0 + row) * E_DIM + k0 + kq]);
            As[kq + 0][row] = v.x; As[kq + 1][row] = v.y;
            As[kq + 2][row] = v.z; As[kq + 3][row] = v.w;
        }
        {
            int row = tid >> 4, cq = (tid & 15) << 2;
            *reinterpret_cast<float4*>(&Bs[row][cq]) =
                *reinterpret_cast<const float4*>(&Wv[(k0 + row) * ER + n0 + cq]);
        }
        __syncthreads();
#pragma unroll
        for (int k = 0; k < 16; k++) {
            float4 a0 = *reinterpret_cast<const float4*>(&As[k][ty * 8]);
            float4 a1 = *reinterpret_cast<const float4*>(&As[k][ty * 8 + 4]);
            float4 bq4 = *reinterpret_cast<const float4*>(&Bs[k][tx * 4]);
            float av[8] = {a0.x, a0.y, a0.z, a0.w, a1.x, a1.y, a1.z, a1.w};
            float bw[4] = {bq4.x, bq4.y, bq4.z, bq4.w};
#pragma unroll
            for (int i = 0; i < 8; i++)
#pragma unroll
                for (int j = 0; j < 4; j++)
                    acc[i][j] = fmaf(av[i], bw[j], acc[i][j]);
        }
        __syncthreads();
    }

    // Epilogue: this thread's 4 cols are rules r0..r0+3 of d-local dl.
    const float scale = 0.125f;
    int r0 = (tx & 3) << 2;
    int dl = tx >> 2;
    float4 bb = *reinterpret_cast<const float4*>(&bv[n0 + tx * 4]);
    float bl[4] = {bb.x, bb.y, bb.z, bb.w};
#pragma unroll
    for (int i = 0; i < 8; i++) {
        int row = ty * 8 + i;
        float p = 0.f;
#pragma unroll
        for (int j = 0; j < 4; j++)
            p = fmaf((acc[i][j] + bl[j]) * scale, attn_s[row][r0 + j], p);
        red_s[row][dl][tx & 3] = p;
    }
    __syncthreads();

    // 512 outputs (128 tokens x 4 d), 2 per thread; write with torch scramble:
    // u = h*2048 + s;  mid[b, u/12, (u%12)*64 + d]
#pragma unroll
    for (int it = 0; it < 2; it++) {
        int f = tid + it * 256;            // 0..511
        int row = f >> 2, dl2 = f & 3;
        float v = red_s[row][dl2][0] + red_s[row][dl2][1]
                + red_s[row][dl2][2] + red_s[row][dl2][3];
        int t = m0 + row;
        int b = t >> 11, s = t & 2047;
        int d = dbase + dl2;
        int u = h * 2048 + s;
        int j = u / 12;
        int c = (u - j * 12) * 64 + d;
        g_mid[(b * 2048 + j) * E_DIM + c] = v;
    }
}

// ---------------------------------------------------------------------------
extern "C" void kernel_launch(void* const* d_in, const int* in_sizes, int n_in,
                              void* d_out, int out_size)
{
    const float* query = (const float*)d_in[0];
    // d_in[1] = key (unused by reference)
    const float* value = (const float*)d_in[2];
    const float* rk    = (const float*)d_in[3];
    const float* rw    = (const float*)d_in[4];
    const float* Wq    = (const float*)d_in[5];
    const float* bq    = (const float*)d_in[6];
    const float* Wv    = (const float*)d_in[7];
    const float* bv    = (const float*)d_in[8];
    const float* Wo    = (const float*)d_in[9];
    const float* bo    = (const float*)d_in[10];
    float* out = (float*)d_out;

    const float scale = 0.125f;  // HD^-0.5

    gemm768_kernel<<<dim3(12, 32), 256>>>(query, Wq, bq, nullptr, scale, 0);
    attn_kernel<<<(T_TOK * HN * RN) / 256, 256>>>(rk, rw);
    fused_v_kernel<<<dim3(ER / 64, 32), 256>>>(value, Wv, bv);
    gemm768_kernel<<<dim3(12, 32), 256>>>(nullptr, Wo, bo, out, 1.0f, 1);
}

// round 4
// speedup vs baseline: 2.0078x; 2.0078x over previous
#include <cuda_runtime.h>
#include <cuda_bf16.h>
#include <cstdint>

#define T_TOK 4096
#define E_DIM 768
#define HN 12
#define RN 16
#define HD 64
#define ER 12288
#define K3 2304          // 3 * 768 (split-bf16 concatenated K)
#define NCHUNK 36        // K3 / 64 halves per chunk

// ---------------------------------------------------------------------------
// Scratch (__device__ globals; allocation-free rule)
// ---------------------------------------------------------------------------
__device__ float g_q[T_TOK * E_DIM];
__device__ float g_attn[T_TOK * HN * RN];
__device__ float g_mid[T_TOK * E_DIM];
__device__ __align__(128) __nv_bfloat16 g_A2[(size_t)T_TOK * K3];   // [Vh|Vh|Vl]
__device__ __align__(128) __nv_bfloat16 g_W2[(size_t)ER * K3];      // [Wh|Wl|Wh], [N,K] K-major

// ---------------------------------------------------------------------------
__device__ __forceinline__ uint32_t smem_u32(const void* p) {
    uint32_t a;
    asm("{ .reg .u64 t; cvta.to.shared.u64 t, %1; cvt.u32.u64 %0, t; }" : "=r"(a) : "l"(p));
    return a;
}

#define CP_ASYNC16(dst, src) \
    asm volatile("cp.async.cg.shared.global [%0], [%1], 16;" :: "r"(dst), "l"(src))
#define CP_COMMIT() asm volatile("cp.async.commit_group;" ::: "memory")

__device__ __forceinline__ void ldsm_x4(uint32_t& r0, uint32_t& r1, uint32_t& r2,
                                        uint32_t& r3, uint32_t addr) {
    asm volatile("ldmatrix.sync.aligned.m8n8.x4.shared.b16 {%0,%1,%2,%3}, [%4];"
                 : "=r"(r0), "=r"(r1), "=r"(r2), "=r"(r3) : "r"(addr));
}

__device__ __forceinline__ void mma_bf16(float* c, const uint32_t* a,
                                         uint32_t b0, uint32_t b1) {
    asm volatile(
        "mma.sync.aligned.m16n8k16.row.col.f32.bf16.bf16.f32 "
        "{%0,%1,%2,%3}, {%4,%5,%6,%7}, {%8,%9}, {%0,%1,%2,%3};"
        : "+f"(c[0]), "+f"(c[1]), "+f"(c[2]), "+f"(c[3])
        : "r"(a[0]), "r"(a[1]), "r"(a[2]), "r"(a[3]), "r"(b0), "r"(b1));
}

// ---------------------------------------------------------------------------
// SIMT fp32 GEMM 4096x768x768: C = (A @ W + bias) * scale  (Wq / Wo paths)
// ---------------------------------------------------------------------------
__global__ __launch_bounds__(256) void gemm768_kernel(
    const float* __restrict__ Ap, const float* __restrict__ W,
    const float* __restrict__ bias, float* __restrict__ Cp,
    float scale, int mode)
{
    const float* A = (mode == 0) ? Ap : g_mid;
    float*       C = (mode == 0) ? g_q : Cp;

    __shared__ float As[16][128];
    __shared__ float Bs[16][64];

    int tid = threadIdx.x;
    int tx = tid & 15, ty = tid >> 4;
    int m0 = blockIdx.y * 128;
    int n0 = blockIdx.x * 64;

    float acc[8][4];
#pragma unroll
    for (int i = 0; i < 8; i++)
#pragma unroll
        for (int j = 0; j < 4; j++) acc[i][j] = 0.f;

    for (int k0 = 0; k0 < E_DIM; k0 += 16) {
#pragma unroll
        for (int it = 0; it < 2; it++) {
            int f = tid + it * 256;
            int row = f >> 2, kq = (f & 3) << 2;
            float4 v = *reinterpret_cast<const float4*>(&A[(m0 + row) * E_DIM + k0 + kq]);
            As[kq + 0][row] = v.x; As[kq + 1][row] = v.y;
            As[kq + 2][row] = v.z; As[kq + 3][row] = v.w;
        }
        {
            int row = tid >> 4, cq = (tid & 15) << 2;
            *reinterpret_cast<float4*>(&Bs[row][cq]) =
                *reinterpret_cast<const float4*>(&W[(k0 + row) * E_DIM + n0 + cq]);
        }
        __syncthreads();
#pragma unroll
        for (int k = 0; k < 16; k++) {
            float4 a0 = *reinterpret_cast<const float4*>(&As[k][ty * 8]);
            float4 a1 = *reinterpret_cast<const float4*>(&As[k][ty * 8 + 4]);
            float4 bq4 = *reinterpret_cast<const float4*>(&Bs[k][tx * 4]);
            float av[8] = {a0.x, a0.y, a0.z, a0.w, a1.x, a1.y, a1.z, a1.w};
            float bw[4] = {bq4.x, bq4.y, bq4.z, bq4.w};
#pragma unroll
            for (int i = 0; i < 8; i++)
#pragma unroll
                for (int j = 0; j < 4; j++)
                    acc[i][j] = fmaf(av[i], bw[j], acc[i][j]);
        }
        __syncthreads();
    }

    float4 bb = *reinterpret_cast<const float4*>(&bias[n0 + tx * 4]);
    float bl[4] = {bb.x, bb.y, bb.z, bb.w};
#pragma unroll
    for (int i = 0; i < 8; i++) {
        float4 o;
        o.x = (acc[i][0] + bl[0]) * scale;
        o.y = (acc[i][1] + bl[1]) * scale;
        o.z = (acc[i][2] + bl[2]) * scale;
        o.w = (acc[i][3] + bl[3]) * scale;
        *reinterpret_cast<float4*>(&C[(m0 + ty * 8 + i) * E_DIM + n0 + tx * 4]) = o;
    }
}

// ---------------------------------------------------------------------------
// Fuzzy membership + 16-wide softmax
// ---------------------------------------------------------------------------
__global__ __launch_bounds__(256) void attn_kernel(
    const float* __restrict__ rk, const float* __restrict__ rw)
{
    int gid = blockIdx.x * blockDim.x + threadIdx.x;
    int r  = gid & 15;
    int th = gid >> 4;
    int h  = th % HN;
    int t  = th / HN;

    const float* qp  = &g_q[t * E_DIM + h * HD];
    const float* rkp = &rk[(h * RN + r) * HD];
    const float* rwp = &rw[(h * RN + r) * HD];

    float s = 0.f;
#pragma unroll
    for (int d = 0; d < HD; d++) {
        float diff = (qp[d] - rkp[d]) / rwp[d];
        s = fmaf(diff, diff, s);
    }
    float z = -0.5f * s * (1.0f / 64.0f);

    float m = z;
#pragma unroll
    for (int o = 8; o; o >>= 1) m = fmaxf(m, __shfl_xor_sync(0xffffffffu, m, o));
    float e = expf(z - m);
    float sum = e;
#pragma unroll
    for (int o = 8; o; o >>= 1) sum += __shfl_xor_sync(0xffffffffu, sum, o);

    g_attn[gid] = e / sum;
}

// ---------------------------------------------------------------------------
// Split-bf16 conversions
// ---------------------------------------------------------------------------
__global__ __launch_bounds__(256) void convert_A_kernel(const float* __restrict__ V) {
    int idx = blockIdx.x * 256 + threadIdx.x;
    int t = idx / E_DIM, e = idx - t * E_DIM;
    float v = V[idx];
    __nv_bfloat16 hi = __float2bfloat16(v);
    __nv_bfloat16 lo = __float2bfloat16(v - __bfloat162float(hi));
    size_t base = (size_t)t * K3 + e;
    g_A2[base]        = hi;
    g_A2[base + 768]  = hi;
    g_A2[base + 1536] = lo;
}

// W2 row n: [hi(Wv[:,n]) | lo(Wv[:,n]) | hi(Wv[:,n])], K-major
__global__ __launch_bounds__(256) void convert_W_kernel(const float* __restrict__ Wv) {
    __shared__ float s[32][33];
    int c0 = blockIdx.x * 32, e0 = blockIdx.y * 32;
    int tx = threadIdx.x & 31, ty = threadIdx.x >> 5;
#pragma unroll
    for (int it = 0; it < 4; it++) {
        int er = ty + it * 8;
        s[er][tx] = Wv[(size_t)(e0 + er) * ER + c0 + tx];
    }
    __syncthreads();
#pragma unroll
    for (int it = 0; it < 4; it++) {
        int cr = ty + it * 8;
        float v = s[tx][cr];
        __nv_bfloat16 hi = __float2bfloat16(v);
        __nv_bfloat16 lo = __float2bfloat16(v - __bfloat162float(hi));
        size_t base = (size_t)(c0 + cr) * K3 + e0 + tx;
        g_W2[base]        = hi;
        g_W2[base + 768]  = lo;
        g_W2[base + 1536] = hi;
    }
}

// ---------------------------------------------------------------------------
// mma.sync fused kernel: D[128tok x 128col] = A2 @ W2^T over K=2304 bf16
// CTA 128x128 (one head's 8 d x 16 r), 8 warps (4M x 2N), warp tile 32x64.
// Epilogue: rule softmax-weighted reduction + torch-scramble scatter.
// ---------------------------------------------------------------------------
// smem layout (bytes, after 1024-align):
//   0      : A tiles  2 x 16384
//   32768  : B tiles  2 x 16384
//   65536  : attn_s   float[128][17]  (8704)
//   74240  : bv_s     float[128]      (512)
//   74752  : red      float[128][8]   (4096)
#define FV_SMEM (78848 + 1024)

__global__ __launch_bounds__(256) void fused_v_mma_kernel(const float* __restrict__ bv) {
    extern __shared__ char smraw[];
    char* sm = (char*)(((uintptr_t)smraw + 1023) & ~(uintptr_t)1023);
    uint32_t sbase = smem_u32(sm);
    float* attn_s = reinterpret_cast<float*>(sm + 65536);
    float* bv_s   = reinterpret_cast<float*>(sm + 74240);
    float* red    = reinterpret_cast<float*>(sm + 74752);

    int tid = threadIdx.x;
    int lane = tid & 31, wid = tid >> 5;
    int wm = wid & 3, wn = wid >> 2;
    int m0w = wm * 32, n0w = wn * 64;
    int bx = blockIdx.x, by = blockIdx.y;
    int m0 = by * 128;
    int h = bx >> 3;
    int dbase = (bx & 7) * 8;

    const char* Ab = (const char*)g_A2 + (size_t)m0 * (K3 * 2);
    const char* Bb = (const char*)g_W2 + (size_t)(bx * 128) * (K3 * 2);

    // attn tile + bias while pipeline warms up
#pragma unroll
    for (int it = 0; it < 8; it++) {
        int f = tid + it * 256;
        int row = f >> 4, r = f & 15;
        attn_s[row * 17 + r] = g_attn[(m0 + row) * (HN * RN) + h * RN + r];
    }
    if (tid < 128) bv_s[tid] = bv[bx * 128 + tid];

    auto load_chunk = [&](int kc, int buf) {
        long koff = (long)kc * 128;
        uint32_t Adst = sbase + buf * 16384u;
        uint32_t Bdst = sbase + 32768u + buf * 16384u;
#pragma unroll
        for (int it = 0; it < 4; it++) {
            int f = tid + it * 256;
            int row = f >> 3, cc = f & 7;
            CP_ASYNC16(Adst + row * 128 + (((cc ^ row) & 7) << 4),
                       Ab + (long)row * (K3 * 2) + koff + cc * 16);
        }
#pragma unroll
        for (int it = 0; it < 4; it++) {
            int f = tid + it * 256;
            int row = f >> 3, cc = f & 7;
            CP_ASYNC16(Bdst + row * 128 + (((cc ^ row) & 7) << 4),
                       Bb + (long)row * (K3 * 2) + koff + cc * 16);
        }
        CP_COMMIT();
    };

    float acc[2][8][4];
#pragma unroll
    for (int i = 0; i < 2; i++)
#pragma unroll
        for (int j = 0; j < 8; j++)
#pragma unroll
            for (int e = 0; e < 4; e++) acc[i][j][e] = 0.f;

    // Per-lane ldmatrix address components
    int xr = lane & 7;
    int aRow0 = m0w + (lane & 15);          // + 16*i
    int aU = lane >> 4;                     // k-half select
    int bRowB = n0w + (lane & 7) + ((lane >> 4) << 3);  // + 16*g
    int bU = (lane >> 3) & 1;

    load_chunk(0, 0);

    for (int c = 0; c < NCHUNK; c++) {
        if (c + 1 < NCHUNK) {
            load_chunk(c + 1, (c + 1) & 1);
            asm volatile("cp.async.wait_group 1;" ::: "memory");
        } else {
            asm volatile("cp.async.wait_group 0;" ::: "memory");
        }
        __syncthreads();

        uint32_t Abase = sbase + (c & 1) * 16384u;
        uint32_t Bbase = sbase + 32768u + (c & 1) * 16384u;
#pragma unroll
        for (int s = 0; s < 4; s++) {
            uint32_t a[2][4];
#pragma unroll
            for (int i = 0; i < 2; i++) {
                int u = 2 * s + aU;
                uint32_t addr = Abase + (aRow0 + 16 * i) * 128 + ((u ^ xr) << 4);
                ldsm_x4(a[i][0], a[i][1], a[i][2], a[i][3], addr);
            }
            uint32_t b[4][4];
#pragma unroll
            for (int g = 0; g < 4; g++) {
                int u = 2 * s + bU;
                uint32_t addr = Bbase + (bRowB + 16 * g) * 128 + ((u ^ xr) << 4);
                ldsm_x4(b[g][0], b[g][1], b[g][2], b[g][3], addr);
            }
#pragma unroll
            for (int i = 0; i < 2; i++)
#pragma unroll
                for (int g = 0; g < 4; g++) {
                    mma_bf16(acc[i][2 * g],     a[i], b[g][0], b[g][1]);
                    mma_bf16(acc[i][2 * g + 1], a[i], b[g][2], b[g][3]);
                }
        }
        __syncthreads();
    }

    // ---- Epilogue: attn-weighted rule reduction ----
    int q = lane & 3, rowg = lane >> 2;
#pragma unroll
    for (int i = 0; i < 2; i++) {
#pragma unroll
        for (int half = 0; half < 2; half++) {
            int rowL = m0w + 16 * i + rowg + 8 * half;
            float p[4] = {0.f, 0.f, 0.f, 0.f};
#pragma unroll
            for (int j = 0; j < 8; j++) {
#pragma unroll
                for (int e = 0; e < 2; e++) {
                    int clw = 8 * j + 2 * q + e;            // 0..63 within warp N
                    int cl = n0w + clw;                     // 0..127 within CTA
                    float val = (acc[i][j][half * 2 + e] + bv_s[cl]) * 0.125f;
                    p[clw >> 4] = fmaf(attn_s[rowL * 17 + (cl & 15)], val, p[clw >> 4]);
                }
            }
#pragma unroll
            for (int d = 0; d < 4; d++) {
                p[d] += __shfl_xor_sync(0xffffffffu, p[d], 1);
                p[d] += __shfl_xor_sync(0xffffffffu, p[d], 2);
            }
            if (q == 0) {
                red[rowL * 8 + wn * 4 + 0] = p[0];
                red[rowL * 8 + wn * 4 + 1] = p[1];
                red[rowL * 8 + wn * 4 + 2] = p[2];
                red[rowL * 8 + wn * 4 + 3] = p[3];
            }
        }
    }
    __syncthreads();

    // torch scramble scatter: u = h*2048 + s; mid[b, u/12, (u%12)*64 + d]
    {
        int row = tid >> 1, part = tid & 1;
        float4 v = *reinterpret_cast<float4*>(&red[row * 8 + part * 4]);
        int t = m0 + row;
        int b = t >> 11, s = t & 2047;
        int u = h * 2048 + s;
        int jj = u / 12;
        int col0 = (u - jj * 12) * 64 + dbase + part * 4;
        *reinterpret_cast<float4*>(&g_mid[(size_t)(b * 2048 + jj) * E_DIM + col0]) = v;
    }
}

// ---------------------------------------------------------------------------
extern "C" void kernel_launch(void* const* d_in, const int* in_sizes, int n_in,
                              void* d_out, int out_size)
{
    const float* query = (const float*)d_in[0];
    const float* value = (const float*)d_in[2];
    const float* rk    = (const float*)d_in[3];
    const float* rw    = (const float*)d_in[4];
    const float* Wq    = (const float*)d_in[5];
    const float* bq    = (const float*)d_in[6];
    const float* Wv    = (const float*)d_in[7];
    const float* bv    = (const float*)d_in[8];
    const float* Wo    = (const float*)d_in[9];
    const float* bo    = (const float*)d_in[10];
    float* out = (float*)d_out;

    cudaFuncSetAttribute(fused_v_mma_kernel,
                         cudaFuncAttributeMaxDynamicSharedMemorySize, FV_SMEM);

    gemm768_kernel<<<dim3(12, 32), 256>>>(query, Wq, bq, nullptr, 0.125f, 0);
    attn_kernel<<<(T_TOK * HN * RN) / 256, 256>>>(rk, rw);
    convert_A_kernel<<<(T_TOK * E_DIM) / 256, 256>>>(value);
    convert_W_kernel<<<dim3(ER / 32, E_DIM / 32), 256>>>(Wv);
    fused_v_mma_kernel<<<dim3(ER / 128, T_TOK / 128), 256, FV_SMEM>>>(bv);
    gemm768_kernel<<<dim3(12, 32), 256>>>(nullptr, Wo, bo, out, 1.0f, 1);
}

// round 5
// speedup vs baseline: 2.2664x; 1.1288x over previous
#include <cuda_runtime.h>
#include <cuda_bf16.h>
#include <cstdint>

#define T_TOK 4096
#define E_DIM 768
#define HN 12
#define RN 16
#define HD 64
#define ER 12288
#define K3 2304          // 3 * 768 (split-bf16 concatenated K)
#define NCHUNK 36        // K3 / 64 halves per chunk

// ---------------------------------------------------------------------------
// Scratch (__device__ globals; allocation-free rule)
// ---------------------------------------------------------------------------
__device__ float g_q[T_TOK * E_DIM];
__device__ float g_attn[T_TOK * HN * RN];
__device__ float g_mid[T_TOK * E_DIM];
__device__ __align__(128) __nv_bfloat16 g_A2[(size_t)T_TOK * K3];    // value  [Vh|Vh|Vl]
__device__ __align__(128) __nv_bfloat16 g_A2x[(size_t)T_TOK * K3];   // query, then mid
__device__ __align__(128) __nv_bfloat16 g_W2[(size_t)ER * K3];       // Wv  [Wh|Wl|Wh], [N,K] K-major
__device__ __align__(128) __nv_bfloat16 g_W2q[(size_t)E_DIM * K3];   // Wq
__device__ __align__(128) __nv_bfloat16 g_W2o[(size_t)E_DIM * K3];   // Wo

// ---------------------------------------------------------------------------
__device__ __forceinline__ uint32_t smem_u32(const void* p) {
    uint32_t a;
    asm("{ .reg .u64 t; cvta.to.shared.u64 t, %1; cvt.u32.u64 %0, t; }" : "=r"(a) : "l"(p));
    return a;
}

#define CP_ASYNC16(dst, src) \
    asm volatile("cp.async.cg.shared.global [%0], [%1], 16;" :: "r"(dst), "l"(src))
#define CP_COMMIT() asm volatile("cp.async.commit_group;" ::: "memory")

__device__ __forceinline__ void ldsm_x4(uint32_t& r0, uint32_t& r1, uint32_t& r2,
                                        uint32_t& r3, uint32_t addr) {
    asm volatile("ldmatrix.sync.aligned.m8n8.x4.shared.b16 {%0,%1,%2,%3}, [%4];"
                 : "=r"(r0), "=r"(r1), "=r"(r2), "=r"(r3) : "r"(addr));
}

__device__ __forceinline__ void mma_bf16(float* c, const uint32_t* a,
                                         uint32_t b0, uint32_t b1) {
    asm volatile(
        "mma.sync.aligned.m16n8k16.row.col.f32.bf16.bf16.f32 "
        "{%0,%1,%2,%3}, {%4,%5,%6,%7}, {%8,%9}, {%0,%1,%2,%3};"
        : "+f"(c[0]), "+f"(c[1]), "+f"(c[2]), "+f"(c[3])
        : "r"(a[0]), "r"(a[1]), "r"(a[2]), "r"(a[3]), "r"(b0), "r"(b1));
}

// ---------------------------------------------------------------------------
// Fuzzy membership + 16-wide softmax
// ---------------------------------------------------------------------------
__global__ __launch_bounds__(256) void attn_kernel(
    const float* __restrict__ rk, const float* __restrict__ rw)
{
    int gid = blockIdx.x * blockDim.x + threadIdx.x;
    int r  = gid & 15;
    int th = gid >> 4;
    int h  = th % HN;
    int t  = th / HN;

    const float* qp  = &g_q[t * E_DIM + h * HD];
    const float* rkp = &rk[(h * RN + r) * HD];
    const float* rwp = &rw[(h * RN + r) * HD];

    float s = 0.f;
#pragma unroll
    for (int d = 0; d < HD; d++) {
        float diff = (qp[d] - rkp[d]) / rwp[d];
        s = fmaf(diff, diff, s);
    }
    float z = -0.5f * s * (1.0f / 64.0f);

    float m = z;
#pragma unroll
    for (int o = 8; o; o >>= 1) m = fmaxf(m, __shfl_xor_sync(0xffffffffu, m, o));
    float e = expf(z - m);
    float sum = e;
#pragma unroll
    for (int o = 8; o; o >>= 1) sum += __shfl_xor_sync(0xffffffffu, sum, o);

    g_attn[gid] = e / sum;
}

// ---------------------------------------------------------------------------
// Split-bf16 conversions (generalized src/dst)
// ---------------------------------------------------------------------------
__global__ __launch_bounds__(256) void convert_A_kernel(
    const float* __restrict__ src, __nv_bfloat16* __restrict__ dst)
{
    int idx = blockIdx.x * 256 + threadIdx.x;
    int t = idx / E_DIM, e = idx - t * E_DIM;
    float v = src[idx];
    __nv_bfloat16 hi = __float2bfloat16(v);
    __nv_bfloat16 lo = __float2bfloat16(v - __bfloat162float(hi));
    size_t base = (size_t)t * K3 + e;
    dst[base]        = hi;
    dst[base + 768]  = hi;
    dst[base + 1536] = lo;
}

// W [768, ldW] -> dst row n: [hi(W[:,n]) | lo(W[:,n]) | hi(W[:,n])], K-major
__global__ __launch_bounds__(256) void convert_W_kernel(
    const float* __restrict__ W, __nv_bfloat16* __restrict__ dst, int ldW)
{
    __shared__ float s[32][33];
    int c0 = blockIdx.x * 32, e0 = blockIdx.y * 32;
    int tx = threadIdx.x & 31, ty = threadIdx.x >> 5;
#pragma unroll
    for (int it = 0; it < 4; it++) {
        int er = ty + it * 8;
        s[er][tx] = W[(size_t)(e0 + er) * ldW + c0 + tx];
    }
    __syncthreads();
#pragma unroll
    for (int it = 0; it < 4; it++) {
        int cr = ty + it * 8;
        float v = s[tx][cr];
        __nv_bfloat16 hi = __float2bfloat16(v);
        __nv_bfloat16 lo = __float2bfloat16(v - __bfloat162float(hi));
        size_t base = (size_t)(c0 + cr) * K3 + e0 + tx;
        dst[base]        = hi;
        dst[base + 768]  = lo;
        dst[base + 1536] = hi;
    }
}

// ---------------------------------------------------------------------------
// Generic split-bf16 mma.sync GEMM: C[4096 x 768] = (A2 @ W2^T + bias) * scale
// Same 128x128 CTA / 8-warp / double-buffered cp.async mainloop as the fused
// kernel; plain bias+scale epilogue with direct float2 stores.
// ---------------------------------------------------------------------------
#define MG_SMEM (66560 + 1024)

__global__ __launch_bounds__(256) void mma_gemm_kernel(
    const __nv_bfloat16* __restrict__ A2, const __nv_bfloat16* __restrict__ W2,
    const float* __restrict__ bias, float* __restrict__ C, float scale)
{
    extern __shared__ char smraw[];
    char* sm = (char*)(((uintptr_t)smraw + 1023) & ~(uintptr_t)1023);
    uint32_t sbase = smem_u32(sm);
    float* bias_s = reinterpret_cast<float*>(sm + 65536);

    int tid = threadIdx.x;
    int lane = tid & 31, wid = tid >> 5;
    int wm = wid & 3, wn = wid >> 2;
    int m0w = wm * 32, n0w = wn * 64;
    int bx = blockIdx.x, by = blockIdx.y;
    int m0 = by * 128;

    const char* Ab = (const char*)A2 + (size_t)m0 * (K3 * 2);
    const char* Bb = (const char*)W2 + (size_t)(bx * 128) * (K3 * 2);

    if (tid < 128) bias_s[tid] = bias[bx * 128 + tid];

    auto load_chunk = [&](int kc, int buf) {
        long koff = (long)kc * 128;
        uint32_t Adst = sbase + buf * 16384u;
        uint32_t Bdst = sbase + 32768u + buf * 16384u;
#pragma unroll
        for (int it = 0; it < 4; it++) {
            int f = tid + it * 256;
            int row = f >> 3, cc = f & 7;
            CP_ASYNC16(Adst + row * 128 + (((cc ^ row) & 7) << 4),
                       Ab + (long)row * (K3 * 2) + koff + cc * 16);
        }
#pragma unroll
        for (int it = 0; it < 4; it++) {
            int f = tid + it * 256;
            int row = f >> 3, cc = f & 7;
            CP_ASYNC16(Bdst + row * 128 + (((cc ^ row) & 7) << 4),
                       Bb + (long)row * (K3 * 2) + koff + cc * 16);
        }
        CP_COMMIT();
    };

    float acc[2][8][4];
#pragma unroll
    for (int i = 0; i < 2; i++)
#pragma unroll
        for (int j = 0; j < 8; j++)
#pragma unroll
            for (int e = 0; e < 4; e++) acc[i][j][e] = 0.f;

    int xr = lane & 7;
    int aRow0 = m0w + (lane & 15);
    int aU = lane >> 4;
    int bRowB = n0w + (lane & 7) + ((lane >> 4) << 3);
    int bU = (lane >> 3) & 1;

    load_chunk(0, 0);

    for (int c = 0; c < NCHUNK; c++) {
        if (c + 1 < NCHUNK) {
            load_chunk(c + 1, (c + 1) & 1);
            asm volatile("cp.async.wait_group 1;" ::: "memory");
        } else {
            asm volatile("cp.async.wait_group 0;" ::: "memory");
        }
        __syncthreads();

        uint32_t Abase = sbase + (c & 1) * 16384u;
        uint32_t Bbase = sbase + 32768u + (c & 1) * 16384u;
#pragma unroll
        for (int s = 0; s < 4; s++) {
            uint32_t a[2][4];
#pragma unroll
            for (int i = 0; i < 2; i++) {
                int u = 2 * s + aU;
                uint32_t addr = Abase + (aRow0 + 16 * i) * 128 + ((u ^ xr) << 4);
                ldsm_x4(a[i][0], a[i][1], a[i][2], a[i][3], addr);
            }
            uint32_t b[4][4];
#pragma unroll
            for (int g = 0; g < 4; g++) {
                int u = 2 * s + bU;
                uint32_t addr = Bbase + (bRowB + 16 * g) * 128 + ((u ^ xr) << 4);
                ldsm_x4(b[g][0], b[g][1], b[g][2], b[g][3], addr);
            }
#pragma unroll
            for (int i = 0; i < 2; i++)
#pragma unroll
                for (int g = 0; g < 4; g++) {
                    mma_bf16(acc[i][2 * g],     a[i], b[g][0], b[g][1]);
                    mma_bf16(acc[i][2 * g + 1], a[i], b[g][2], b[g][3]);
                }
        }
        __syncthreads();
    }

    // Epilogue: (acc + bias) * scale -> C, row-major [4096][768]
#pragma unroll
    for (int i = 0; i < 2; i++) {
        int rowL = m0 + m0w + 16 * i + (lane >> 2);
#pragma unroll
        for (int j = 0; j < 8; j++) {
            int colL = n0w + 8 * j + 2 * (lane & 3);
            int colG = bx * 128 + colL;
            float2 v0 = make_float2((acc[i][j][0] + bias_s[colL]) * scale,
                                    (acc[i][j][1] + bias_s[colL + 1]) * scale);
            float2 v1 = make_float2((acc[i][j][2] + bias_s[colL]) * scale,
                                    (acc[i][j][3] + bias_s[colL + 1]) * scale);
            *reinterpret_cast<float2*>(&C[(size_t)rowL * E_DIM + colG]) = v0;
            *reinterpret_cast<float2*>(&C[(size_t)(rowL + 8) * E_DIM + colG]) = v1;
        }
    }
}

// ---------------------------------------------------------------------------
// mma.sync fused kernel (unchanged from the passing round-4 version):
// D[128tok x 128col] = A2 @ W2^T over K=2304 bf16; CTA 128x128 (one head's
// 8 d x 16 r), 8 warps (4M x 2N); epilogue: attn-weighted rule reduction +
// torch-scramble scatter.
// ---------------------------------------------------------------------------
#define FV_SMEM (78848 + 1024)

__global__ __launch_bounds__(256) void fused_v_mma_kernel(const float* __restrict__ bv) {
    extern __shared__ char smraw[];
    char* sm = (char*)(((uintptr_t)smraw + 1023) & ~(uintptr_t)1023);
    uint32_t sbase = smem_u32(sm);
    float* attn_s = reinterpret_cast<float*>(sm + 65536);
    float* bv_s   = reinterpret_cast<float*>(sm + 74240);
    float* red    = reinterpret_cast<float*>(sm + 74752);

    int tid = threadIdx.x;
    int lane = tid & 31, wid = tid >> 5;
    int wm = wid & 3, wn = wid >> 2;
    int m0w = wm * 32, n0w = wn * 64;
    int bx = blockIdx.x, by = blockIdx.y;
    int m0 = by * 128;
    int h = bx >> 3;
    int dbase = (bx & 7) * 8;

    const char* Ab = (const char*)g_A2 + (size_t)m0 * (K3 * 2);
    const char* Bb = (const char*)g_W2 + (size_t)(bx * 128) * (K3 * 2);

#pragma unroll
    for (int it = 0; it < 8; it++) {
        int f = tid + it * 256;
        int row = f >> 4, r = f & 15;
        attn_s[row * 17 + r] = g_attn[(m0 + row) * (HN * RN) + h * RN + r];
    }
    if (tid < 128) bv_s[tid] = bv[bx * 128 + tid];

    auto load_chunk = [&](int kc, int buf) {
        long koff = (long)kc * 128;
        uint32_t Adst = sbase + buf * 16384u;
        uint32_t Bdst = sbase + 32768u + buf * 16384u;
#pragma unroll
        for (int it = 0; it < 4; it++) {
            int f = tid + it * 256;
            int row = f >> 3, cc = f & 7;
            CP_ASYNC16(Adst + row * 128 + (((cc ^ row) & 7) << 4),
                       Ab + (long)row * (K3 * 2) + koff + cc * 16);
        }
#pragma unroll
        for (int it = 0; it < 4; it++) {
            int f = tid + it * 256;
            int row = f >> 3, cc = f & 7;
            CP_ASYNC16(Bdst + row * 128 + (((cc ^ row) & 7) << 4),
                       Bb + (long)row * (K3 * 2) + koff + cc * 16);
        }
        CP_COMMIT();
    };

    float acc[2][8][4];
#pragma unroll
    for (int i = 0; i < 2; i++)
#pragma unroll
        for (int j = 0; j < 8; j++)
#pragma unroll
            for (int e = 0; e < 4; e++) acc[i][j][e] = 0.f;

    int xr = lane & 7;
    int aRow0 = m0w + (lane & 15);
    int aU = lane >> 4;
    int bRowB = n0w + (lane & 7) + ((lane >> 4) << 3);
    int bU = (lane >> 3) & 1;

    load_chunk(0, 0);

    for (int c = 0; c < NCHUNK; c++) {
        if (c + 1 < NCHUNK) {
            load_chunk(c + 1, (c + 1) & 1);
            asm volatile("cp.async.wait_group 1;" ::: "memory");
        } else {
            asm volatile("cp.async.wait_group 0;" ::: "memory");
        }
        __syncthreads();

        uint32_t Abase = sbase + (c & 1) * 16384u;
        uint32_t Bbase = sbase + 32768u + (c & 1) * 16384u;
#pragma unroll
        for (int s = 0; s < 4; s++) {
            uint32_t a[2][4];
#pragma unroll
            for (int i = 0; i < 2; i++) {
                int u = 2 * s + aU;
                uint32_t addr = Abase + (aRow0 + 16 * i) * 128 + ((u ^ xr) << 4);
                ldsm_x4(a[i][0], a[i][1], a[i][2], a[i][3], addr);
            }
            uint32_t b[4][4];
#pragma unroll
            for (int g = 0; g < 4; g++) {
                int u = 2 * s + bU;
                uint32_t addr = Bbase + (bRowB + 16 * g) * 128 + ((u ^ xr) << 4);
                ldsm_x4(b[g][0], b[g][1], b[g][2], b[g][3], addr);
            }
#pragma unroll
            for (int i = 0; i < 2; i++)
#pragma unroll
                for (int g = 0; g < 4; g++) {
                    mma_bf16(acc[i][2 * g],     a[i], b[g][0], b[g][1]);
                    mma_bf16(acc[i][2 * g + 1], a[i], b[g][2], b[g][3]);
                }
        }
        __syncthreads();
    }

    // ---- Epilogue: attn-weighted rule reduction ----
    int q = lane & 3, rowg = lane >> 2;
#pragma unroll
    for (int i = 0; i < 2; i++) {
#pragma unroll
        for (int half = 0; half < 2; half++) {
            int rowL = m0w + 16 * i + rowg + 8 * half;
            float p[4] = {0.f, 0.f, 0.f, 0.f};
#pragma unroll
            for (int j = 0; j < 8; j++) {
#pragma unroll
                for (int e = 0; e < 2; e++) {
                    int clw = 8 * j + 2 * q + e;
                    int cl = n0w + clw;
                    float val = (acc[i][j][half * 2 + e] + bv_s[cl]) * 0.125f;
                    p[clw >> 4] = fmaf(attn_s[rowL * 17 + (cl & 15)], val, p[clw >> 4]);
                }
            }
#pragma unroll
            for (int d = 0; d < 4; d++) {
                p[d] += __shfl_xor_sync(0xffffffffu, p[d], 1);
                p[d] += __shfl_xor_sync(0xffffffffu, p[d], 2);
            }
            if (q == 0) {
                red[rowL * 8 + wn * 4 + 0] = p[0];
                red[rowL * 8 + wn * 4 + 1] = p[1];
                red[rowL * 8 + wn * 4 + 2] = p[2];
                red[rowL * 8 + wn * 4 + 3] = p[3];
            }
        }
    }
    __syncthreads();

    {
        int row = tid >> 1, part = tid & 1;
        float4 v = *reinterpret_cast<float4*>(&red[row * 8 + part * 4]);
        int t = m0 + row;
        int b = t >> 11, s = t & 2047;
        int u = h * 2048 + s;
        int jj = u / 12;
        int col0 = (u - jj * 12) * 64 + dbase + part * 4;
        *reinterpret_cast<float4*>(&g_mid[(size_t)(b * 2048 + jj) * E_DIM + col0]) = v;
    }
}

// ---------------------------------------------------------------------------
extern "C" void kernel_launch(void* const* d_in, const int* in_sizes, int n_in,
                              void* d_out, int out_size)
{
    const float* query = (const float*)d_in[0];
    const float* value = (const float*)d_in[2];
    const float* rk    = (const float*)d_in[3];
    const float* rw    = (const float*)d_in[4];
    const float* Wq    = (const float*)d_in[5];
    const float* bq    = (const float*)d_in[6];
    const float* Wv    = (const float*)d_in[7];
    const float* bv    = (const float*)d_in[8];
    const float* Wo    = (const float*)d_in[9];
    const float* bo    = (const float*)d_in[10];
    float* out = (float*)d_out;

    cudaFuncSetAttribute(fused_v_mma_kernel,
                         cudaFuncAttributeMaxDynamicSharedMemorySize, FV_SMEM);
    cudaFuncSetAttribute(mma_gemm_kernel,
                         cudaFuncAttributeMaxDynamicSharedMemorySize, MG_SMEM);

    __nv_bfloat16 *A2, *A2x, *W2, *W2q, *W2o;
    float *qbuf;
    cudaGetSymbolAddress((void**)&A2,  g_A2);
    cudaGetSymbolAddress((void**)&A2x, g_A2x);
    cudaGetSymbolAddress((void**)&W2,  g_W2);
    cudaGetSymbolAddress((void**)&W2q, g_W2q);
    cudaGetSymbolAddress((void**)&W2o, g_W2o);
    cudaGetSymbolAddress((void**)&qbuf, g_q);
    float* midbuf;
    cudaGetSymbolAddress((void**)&midbuf, g_mid);

    // q-projection (split-bf16 tensor-core GEMM) + fuzzy attn
    convert_A_kernel<<<(T_TOK * E_DIM) / 256, 256>>>(query, A2x);
    convert_W_kernel<<<dim3(E_DIM / 32, E_DIM / 32), 256>>>(Wq, W2q, E_DIM);
    mma_gemm_kernel<<<dim3(E_DIM / 128, T_TOK / 128), 256, MG_SMEM>>>(
        A2x, W2q, bq, qbuf, 0.125f);
    attn_kernel<<<(T_TOK * HN * RN) / 256, 256>>>(rk, rw);

    // fused value-path GEMM + rule reduction
    convert_A_kernel<<<(T_TOK * E_DIM) / 256, 256>>>(value, A2);
    convert_W_kernel<<<dim3(ER / 32, E_DIM / 32), 256>>>(Wv, W2, ER);
    fused_v_mma_kernel<<<dim3(ER / 128, T_TOK / 128), 256, FV_SMEM>>>(bv);

    // output projection (split-bf16 tensor-core GEMM)
    convert_A_kernel<<<(T_TOK * E_DIM) / 256, 256>>>(midbuf, A2x);
    convert_W_kernel<<<dim3(E_DIM / 32, E_DIM / 32), 256>>>(Wo, W2o, E_DIM);
    mma_gemm_kernel<<<dim3(E_DIM / 128, T_TOK / 128), 256, MG_SMEM>>>(
        A2x, W2o, bo, out, 1.0f);
}

// round 7
// speedup vs baseline: 3.3290x; 1.4689x over previous
#include <cuda_runtime.h>
#include <cuda_bf16.h>
#include <cstdint>

#define T_TOK 4096
#define E_DIM 768
#define HN 12
#define RN 16
#define HD 64
#define ER 12288
#define K3 2304          // 3 * 768 (split-bf16 concatenated K)
#define NCHUNK 36        // K3 / 64 halves per chunk

// ---------------------------------------------------------------------------
// Scratch (__device__ globals; allocation-free rule)
// ---------------------------------------------------------------------------
__device__ float g_q[T_TOK * E_DIM];
__device__ float g_attn[T_TOK * HN * RN];
__device__ float g_mid[T_TOK * E_DIM];
__device__ __align__(128) __nv_bfloat16 g_A2[(size_t)T_TOK * K3];    // value  [Vh|Vh|Vl]
__device__ __align__(128) __nv_bfloat16 g_A2x[(size_t)T_TOK * K3];   // query, then mid
__device__ __align__(128) __nv_bfloat16 g_W2[(size_t)ER * K3];       // Wv  [Wh|Wl|Wh], [N,K] K-major
__device__ __align__(128) __nv_bfloat16 g_W2q[(size_t)E_DIM * K3];   // Wq
__device__ __align__(128) __nv_bfloat16 g_W2o[(size_t)E_DIM * K3];   // Wo

// ---------------------------------------------------------------------------
__device__ __forceinline__ uint32_t smem_u32(const void* p) {
    uint32_t a;
    asm("{ .reg .u64 t; cvta.to.shared.u64 t, %1; cvt.u32.u64 %0, t; }" : "=r"(a) : "l"(p));
    return a;
}

#define CP_ASYNC16(dst, src) \
    asm volatile("cp.async.cg.shared.global [%0], [%1], 16;" :: "r"(dst), "l"(src))
#define CP_COMMIT() asm volatile("cp.async.commit_group;" ::: "memory")

__device__ __forceinline__ void ldsm_x4(uint32_t& r0, uint32_t& r1, uint32_t& r2,
                                        uint32_t& r3, uint32_t addr) {
    asm volatile("ldmatrix.sync.aligned.m8n8.x4.shared.b16 {%0,%1,%2,%3}, [%4];"
                 : "=r"(r0), "=r"(r1), "=r"(r2), "=r"(r3) : "r"(addr));
}

__device__ __forceinline__ void mma_bf16(float* c, const uint32_t* a,
                                         uint32_t b0, uint32_t b1) {
    asm volatile(
        "mma.sync.aligned.m16n8k16.row.col.f32.bf16.bf16.f32 "
        "{%0,%1,%2,%3}, {%4,%5,%6,%7}, {%8,%9}, {%0,%1,%2,%3};"
        : "+f"(c[0]), "+f"(c[1]), "+f"(c[2]), "+f"(c[3])
        : "r"(a[0]), "r"(a[1]), "r"(a[2]), "r"(a[3]), "r"(b0), "r"(b1));
}

// ---------------------------------------------------------------------------
// Fuzzy membership + 16-wide softmax — smem-staged, conflict-free version.
// Block: 512 threads = 32 tokens x 16 rules; grid (T/32, H).
// rk and iw=1/rw^2 staged transposed [d][r]; q tile staged with pad-68 rows.
// ---------------------------------------------------------------------------
__global__ __launch_bounds__(512) void attn_kernel(
    const float* __restrict__ rk, const float* __restrict__ rw)
{
    __shared__ float rkT[HD * RN];      // [d][r]
    __shared__ float iwT[HD * RN];      // [d][r]
    __shared__ float q_s[32 * 68];      // [tl][d], pad 68

    int tid = threadIdx.x;
    int t0 = blockIdx.x * 32;
    int h  = blockIdx.y;

    // stage rk and iw (transposed)
#pragma unroll
    for (int it = 0; it < 2; it++) {
        int idx = tid + it * 512;               // 0..1023
        int r = idx >> 6, d = idx & 63;
        float k = rk[h * (RN * HD) + idx];
        float w = rw[h * (RN * HD) + idx];
        rkT[d * RN + r] = k;
        iwT[d * RN + r] = 1.0f / (w * w);
    }
    // stage q tile: 32 tokens x 64 d (float4 loads)
    {
        int row = tid >> 4, c = tid & 15;       // 512 = 32 rows x 16 float4
        float4 v = *reinterpret_cast<const float4*>(
            &g_q[(size_t)(t0 + row) * E_DIM + h * HD + c * 4]);
        *reinterpret_cast<float4*>(&q_s[row * 68 + c * 4]) = v;
    }
    __syncthreads();

    int r  = tid & 15;
    int tl = tid >> 4;

    float s = 0.f;
#pragma unroll
    for (int d = 0; d < HD; d++) {
        float diff = q_s[tl * 68 + d] - rkT[d * RN + r];
        s = fmaf(diff * diff, iwT[d * RN + r], s);
    }
    float z = -0.5f * s * (1.0f / 64.0f);

    float m = z;
#pragma unroll
    for (int o = 8; o; o >>= 1) m = fmaxf(m, __shfl_xor_sync(0xffffffffu, m, o));
    float e = expf(z - m);
    float sum = e;
#pragma unroll
    for (int o = 8; o; o >>= 1) sum += __shfl_xor_sync(0xffffffffu, sum, o);

    g_attn[(size_t)(t0 + tl) * (HN * RN) + h * RN + r] = e / sum;
}

// ---------------------------------------------------------------------------
// Split-bf16 conversions (generalized src/dst)
// ---------------------------------------------------------------------------
__global__ __launch_bounds__(256) void convert_A_kernel(
    const float* __restrict__ src, __nv_bfloat16* __restrict__ dst)
{
    int idx = blockIdx.x * 256 + threadIdx.x;
    int t = idx / E_DIM, e = idx - t * E_DIM;
    float v = src[idx];
    __nv_bfloat16 hi = __float2bfloat16(v);
    __nv_bfloat16 lo = __float2bfloat16(v - __bfloat162float(hi));
    size_t base = (size_t)t * K3 + e;
    dst[base]        = hi;
    dst[base + 768]  = hi;
    dst[base + 1536] = lo;
}

// W [768, ldW] -> dst row n: [hi(W[:,n]) | lo(W[:,n]) | hi(W[:,n])], K-major
__global__ __launch_bounds__(256) void convert_W_kernel(
    const float* __restrict__ W, __nv_bfloat16* __restrict__ dst, int ldW)
{
    __shared__ float s[32][33];
    int c0 = blockIdx.x * 32, e0 = blockIdx.y * 32;
    int tx = threadIdx.x & 31, ty = threadIdx.x >> 5;
#pragma unroll
    for (int it = 0; it < 4; it++) {
        int er = ty + it * 8;
        s[er][tx] = W[(size_t)(e0 + er) * ldW + c0 + tx];
    }
    __syncthreads();
#pragma unroll
    for (int it = 0; it < 4; it++) {
        int cr = ty + it * 8;
        float v = s[tx][cr];
        __nv_bfloat16 hi = __float2bfloat16(v);
        __nv_bfloat16 lo = __float2bfloat16(v - __bfloat162float(hi));
        size_t base = (size_t)(c0 + cr) * K3 + e0 + tx;
        dst[base]        = hi;
        dst[base + 768]  = lo;
        dst[base + 1536] = hi;
    }
}

// ---------------------------------------------------------------------------
// Generic split-bf16 mma.sync GEMM: C[4096 x 768] = (A2 @ W2^T + bias) * scale
// ---------------------------------------------------------------------------
#define MG_SMEM (66560 + 1024)

__global__ __launch_bounds__(256) void mma_gemm_kernel(
    const __nv_bfloat16* __restrict__ A2, const __nv_bfloat16* __restrict__ W2,
    const float* __restrict__ bias, float* __restrict__ C, float scale)
{
    extern __shared__ char smraw[];
    char* sm = (char*)(((uintptr_t)smraw + 1023) & ~(uintptr_t)1023);
    uint32_t sbase = smem_u32(sm);
    float* bias_s = reinterpret_cast<float*>(sm + 65536);

    int tid = threadIdx.x;
    int lane = tid & 31, wid = tid >> 5;
    int wm = wid & 3, wn = wid >> 2;
    int m0w = wm * 32, n0w = wn * 64;
    int bx = blockIdx.x, by = blockIdx.y;
    int m0 = by * 128;

    const char* Ab = (const char*)A2 + (size_t)m0 * (K3 * 2);
    const char* Bb = (const char*)W2 + (size_t)(bx * 128) * (K3 * 2);

    if (tid < 128) bias_s[tid] = bias[bx * 128 + tid];

    auto load_chunk = [&](int kc, int buf) {
        long koff = (long)kc * 128;
        uint32_t Adst = sbase + buf * 16384u;
        uint32_t Bdst = sbase + 32768u + buf * 16384u;
#pragma unroll
        for (int it = 0; it < 4; it++) {
            int f = tid + it * 256;
            int row = f >> 3, cc = f & 7;
            CP_ASYNC16(Adst + row * 128 + (((cc ^ row) & 7) << 4),
                       Ab + (long)row * (K3 * 2) + koff + cc * 16);
        }
#pragma unroll
        for (int it = 0; it < 4; it++) {
            int f = tid + it * 256;
            int row = f >> 3, cc = f & 7;
            CP_ASYNC16(Bdst + row * 128 + (((cc ^ row) & 7) << 4),
                       Bb + (long)row * (K3 * 2) + koff + cc * 16);
        }
        CP_COMMIT();
    };

    float acc[2][8][4];
#pragma unroll
    for (int i = 0; i < 2; i++)
#pragma unroll
        for (int j = 0; j < 8; j++)
#pragma unroll
            for (int e = 0; e < 4; e++) acc[i][j][e] = 0.f;

    int xr = lane & 7;
    int aRow0 = m0w + (lane & 15);
    int aU = lane >> 4;
    int bRowB = n0w + (lane & 7) + ((lane >> 4) << 3);
    int bU = (lane >> 3) & 1;

    load_chunk(0, 0);

    for (int c = 0; c < NCHUNK; c++) {
        if (c + 1 < NCHUNK) {
            load_chunk(c + 1, (c + 1) & 1);
            asm volatile("cp.async.wait_group 1;" ::: "memory");
        } else {
            asm volatile("cp.async.wait_group 0;" ::: "memory");
        }
        __syncthreads();

        uint32_t Abase = sbase + (c & 1) * 16384u;
        uint32_t Bbase = sbase + 32768u + (c & 1) * 16384u;
#pragma unroll
        for (int s = 0; s < 4; s++) {
            uint32_t a[2][4];
#pragma unroll
            for (int i = 0; i < 2; i++) {
                int u = 2 * s + aU;
                uint32_t addr = Abase + (aRow0 + 16 * i) * 128 + ((u ^ xr) << 4);
                ldsm_x4(a[i][0], a[i][1], a[i][2], a[i][3], addr);
            }
            uint32_t b[4][4];
#pragma unroll
            for (int g = 0; g < 4; g++) {
                int u = 2 * s + bU;
                uint32_t addr = Bbase + (bRowB + 16 * g) * 128 + ((u ^ xr) << 4);
                ldsm_x4(b[g][0], b[g][1], b[g][2], b[g][3], addr);
            }
#pragma unroll
            for (int i = 0; i < 2; i++)
#pragma unroll
                for (int g = 0; g < 4; g++) {
                    mma_bf16(acc[i][2 * g],     a[i], b[g][0], b[g][1]);
                    mma_bf16(acc[i][2 * g + 1], a[i], b[g][2], b[g][3]);
                }
        }
        __syncthreads();
    }

#pragma unroll
    for (int i = 0; i < 2; i++) {
        int rowL = m0 + m0w + 16 * i + (lane >> 2);
#pragma unroll
        for (int j = 0; j < 8; j++) {
            int colL = n0w + 8 * j + 2 * (lane & 3);
            int colG = bx * 128 + colL;
            float2 v0 = make_float2((acc[i][j][0] + bias_s[colL]) * scale,
                                    (acc[i][j][1] + bias_s[colL + 1]) * scale);
            float2 v1 = make_float2((acc[i][j][2] + bias_s[colL]) * scale,
                                    (acc[i][j][3] + bias_s[colL + 1]) * scale);
            *reinterpret_cast<float2*>(&C[(size_t)rowL * E_DIM + colG]) = v0;
            *reinterpret_cast<float2*>(&C[(size_t)(rowL + 8) * E_DIM + colG]) = v1;
        }
    }
}

// ---------------------------------------------------------------------------
// mma.sync fused kernel (unchanged, proven): value-GEMM + rule reduction.
// ---------------------------------------------------------------------------
#define FV_SMEM (78848 + 1024)

__global__ __launch_bounds__(256) void fused_v_mma_kernel(const float* __restrict__ bv) {
    extern __shared__ char smraw[];
    char* sm = (char*)(((uintptr_t)smraw + 1023) & ~(uintptr_t)1023);
    uint32_t sbase = smem_u32(sm);
    float* attn_s = reinterpret_cast<float*>(sm + 65536);
    float* bv_s   = reinterpret_cast<float*>(sm + 74240);
    float* red    = reinterpret_cast<float*>(sm + 74752);

    int tid = threadIdx.x;
    int lane = tid & 31, wid = tid >> 5;
    int wm = wid & 3, wn = wid >> 2;
    int m0w = wm * 32, n0w = wn * 64;
    int bx = blockIdx.x, by = blockIdx.y;
    int m0 = by * 128;
    int h = bx >> 3;
    int dbase = (bx & 7) * 8;

    const char* Ab = (const char*)g_A2 + (size_t)m0 * (K3 * 2);
    const char* Bb = (const char*)g_W2 + (size_t)(bx * 128) * (K3 * 2);

#pragma unroll
    for (int it = 0; it < 8; it++) {
        int f = tid + it * 256;
        int row = f >> 4, r = f & 15;
        attn_s[row * 17 + r] = g_attn[(m0 + row) * (HN * RN) + h * RN + r];
    }
    if (tid < 128) bv_s[tid] = bv[bx * 128 + tid];

    auto load_chunk = [&](int kc, int buf) {
        long koff = (long)kc * 128;
        uint32_t Adst = sbase + buf * 16384u;
        uint32_t Bdst = sbase + 32768u + buf * 16384u;
#pragma unroll
        for (int it = 0; it < 4; it++) {
            int f = tid + it * 256;
            int row = f >> 3, cc = f & 7;
            CP_ASYNC16(Adst + row * 128 + (((cc ^ row) & 7) << 4),
                       Ab + (long)row * (K3 * 2) + koff + cc * 16);
        }
#pragma unroll
        for (int it = 0; it < 4; it++) {
            int f = tid + it * 256;
            int row = f >> 3, cc = f & 7;
            CP_ASYNC16(Bdst + row * 128 + (((cc ^ row) & 7) << 4),
                       Bb + (long)row * (K3 * 2) + koff + cc * 16);
        }
        CP_COMMIT();
    };

    float acc[2][8][4];
#pragma unroll
    for (int i = 0; i < 2; i++)
#pragma unroll
        for (int j = 0; j < 8; j++)
#pragma unroll
            for (int e = 0; e < 4; e++) acc[i][j][e] = 0.f;

    int xr = lane & 7;
    int aRow0 = m0w + (lane & 15);
    int aU = lane >> 4;
    int bRowB = n0w + (lane & 7) + ((lane >> 4) << 3);
    int bU = (lane >> 3) & 1;

    load_chunk(0, 0);

    for (int c = 0; c < NCHUNK; c++) {
        if (c + 1 < NCHUNK) {
            load_chunk(c + 1, (c + 1) & 1);
            asm volatile("cp.async.wait_group 1;" ::: "memory");
        } else {
            asm volatile("cp.async.wait_group 0;" ::: "memory");
        }
        __syncthreads();

        uint32_t Abase = sbase + (c & 1) * 16384u;
        uint32_t Bbase = sbase + 32768u + (c & 1) * 16384u;
#pragma unroll
        for (int s = 0; s < 4; s++) {
            uint32_t a[2][4];
#pragma unroll
            for (int i = 0; i < 2; i++) {
                int u = 2 * s + aU;
                uint32_t addr = Abase + (aRow0 + 16 * i) * 128 + ((u ^ xr) << 4);
                ldsm_x4(a[i][0], a[i][1], a[i][2], a[i][3], addr);
            }
            uint32_t b[4][4];
#pragma unroll
            for (int g = 0; g < 4; g++) {
                int u = 2 * s + bU;
                uint32_t addr = Bbase + (bRowB + 16 * g) * 128 + ((u ^ xr) << 4);
                ldsm_x4(b[g][0], b[g][1], b[g][2], b[g][3], addr);
            }
#pragma unroll
            for (int i = 0; i < 2; i++)
#pragma unroll
                for (int g = 0; g < 4; g++) {
                    mma_bf16(acc[i][2 * g],     a[i], b[g][0], b[g][1]);
                    mma_bf16(acc[i][2 * g + 1], a[i], b[g][2], b[g][3]);
                }
        }
        __syncthreads();
    }

    int q = lane & 3, rowg = lane >> 2;
#pragma unroll
    for (int i = 0; i < 2; i++) {
#pragma unroll
        for (int half = 0; half < 2; half++) {
            int rowL = m0w + 16 * i + rowg + 8 * half;
            float p[4] = {0.f, 0.f, 0.f, 0.f};
#pragma unroll
            for (int j = 0; j < 8; j++) {
#pragma unroll
                for (int e = 0; e < 2; e++) {
                    int clw = 8 * j + 2 * q + e;
                    int cl = n0w + clw;
                    float val = (acc[i][j][half * 2 + e] + bv_s[cl]) * 0.125f;
                    p[clw >> 4] = fmaf(attn_s[rowL * 17 + (cl & 15)], val, p[clw >> 4]);
                }
            }
#pragma unroll
            for (int d = 0; d < 4; d++) {
                p[d] += __shfl_xor_sync(0xffffffffu, p[d], 1);
                p[d] += __shfl_xor_sync(0xffffffffu, p[d], 2);
            }
            if (q == 0) {
                red[rowL * 8 + wn * 4 + 0] = p[0];
                red[rowL * 8 + wn * 4 + 1] = p[1];
                red[rowL * 8 + wn * 4 + 2] = p[2];
                red[rowL * 8 + wn * 4 + 3] = p[3];
            }
        }
    }
    __syncthreads();

    {
        int row = tid >> 1, part = tid & 1;
        float4 v = *reinterpret_cast<float4*>(&red[row * 8 + part * 4]);
        int t = m0 + row;
        int b = t >> 11, s = t & 2047;
        int u = h * 2048 + s;
        int jj = u / 12;
        int col0 = (u - jj * 12) * 64 + dbase + part * 4;
        *reinterpret_cast<float4*>(&g_mid[(size_t)(b * 2048 + jj) * E_DIM + col0]) = v;
    }
}

// ---------------------------------------------------------------------------
extern "C" void kernel_launch(void* const* d_in, const int* in_sizes, int n_in,
                              void* d_out, int out_size)
{
    const float* query = (const float*)d_in[0];
    const float* value = (const float*)d_in[2];
    const float* rk    = (const float*)d_in[3];
    const float* rw    = (const float*)d_in[4];
    const float* Wq    = (const float*)d_in[5];
    const float* bq    = (const float*)d_in[6];
    const float* Wv    = (const float*)d_in[7];
    const float* bv    = (const float*)d_in[8];
    const float* Wo    = (const float*)d_in[9];
    const float* bo    = (const float*)d_in[10];
    float* out = (float*)d_out;

    cudaFuncSetAttribute(fused_v_mma_kernel,
                         cudaFuncAttributeMaxDynamicSharedMemorySize, FV_SMEM);
    cudaFuncSetAttribute(mma_gemm_kernel,
                         cudaFuncAttributeMaxDynamicSharedMemorySize, MG_SMEM);

    __nv_bfloat16 *A2, *A2x, *W2, *W2q, *W2o;
    float *qbuf;
    cudaGetSymbolAddress((void**)&A2,  g_A2);
    cudaGetSymbolAddress((void**)&A2x, g_A2x);
    cudaGetSymbolAddress((void**)&W2,  g_W2);
    cudaGetSymbolAddress((void**)&W2q, g_W2q);
    cudaGetSymbolAddress((void**)&W2o, g_W2o);
    cudaGetSymbolAddress((void**)&qbuf, g_q);
    float* midbuf;
    cudaGetSymbolAddress((void**)&midbuf, g_mid);

    // q-projection (split-bf16 tensor-core GEMM) + fuzzy attn
    convert_A_kernel<<<(T_TOK * E_DIM) / 256, 256>>>(query, A2x);
    convert_W_kernel<<<dim3(E_DIM / 32, E_DIM / 32), 256>>>(Wq, W2q, E_DIM);
    mma_gemm_kernel<<<dim3(E_DIM / 128, T_TOK / 128), 256, MG_SMEM>>>(
        A2x, W2q, bq, qbuf, 0.125f);
    attn_kernel<<<dim3(T_TOK / 32, HN), 512>>>(rk, rw);

    // fused value-path GEMM + rule reduction
    convert_A_kernel<<<(T_TOK * E_DIM) / 256, 256>>>(value, A2);
    convert_W_kernel<<<dim3(ER / 32, E_DIM / 32), 256>>>(Wv, W2, ER);
    fused_v_mma_kernel<<<dim3(ER / 128, T_TOK / 128), 256, FV_SMEM>>>(bv);

    // output projection (split-bf16 tensor-core GEMM)
    convert_A_kernel<<<(T_TOK * E_DIM) / 256, 256>>>(midbuf, A2x);
    convert_W_kernel<<<dim3(E_DIM / 32, E_DIM / 32), 256>>>(Wo, W2o, E_DIM);
    mma_gemm_kernel<<<dim3(E_DIM / 128, T_TOK / 128), 256, MG_SMEM>>>(
        A2x, W2o, bo, out, 1.0f);
}